// round 5
// baseline (speedup 1.0000x reference)
#include <cuda_runtime.h>
#include <math.h>

// Problem constants
#define NB 8
#define NW 1024
#define ND 1024
#define NR 64
#define NROWS (NB * NW)   // 8192

// ---------------------------------------------------------------------------
// Scratch (static __device__ arrays — no runtime allocation allowed)
// ---------------------------------------------------------------------------
__device__ float g_hnorm[NB * NW * ND];            // 32 MB
__device__ float g_q[NB * NW * NR];                // 2 MB
__device__ float g_k[NB * NW * NR];                // 2 MB
__device__ float g_M[NB * NW * NW];                // 32 MB  (gate*kb + alpha*scores, causal)
__device__ float g_attn[NB * NW * ND];             // 32 MB
__device__ float g_h1[NB * NW * ND];               // 32 MB
__device__ float g_mid[NB * NW * ND];              // 32 MB  (rmsnorm2 output)
__device__ float g_t[NB * NW * 2 * ND];            // 64 MB  (gelu(up) output)
__device__ float g_P[NW * NR];                     // gamma_r^d, d in [0,1024)
__device__ float g_Pinv[64 * NR];                  // gamma_r^-d, d in [0,64)
__device__ float g_scal[2];                        // gate, alpha

// ---------------------------------------------------------------------------
// Init: gamma tables + scalar gates
// grid: <<<1024, 64>>>
// ---------------------------------------------------------------------------
__global__ void k_init(const float* __restrict__ decay_logit,
                       const float* __restrict__ gate_logit,
                       const float* __restrict__ alpha_logit) {
    int r = threadIdx.x;      // 0..63
    int d = blockIdx.x;       // 0..1023
    float dl = decay_logit[r];
    float sg = 1.0f / (1.0f + expf(-dl));
    float gamma = 0.15f + 0.85f * sg;                 // GAMMA_MIN + (MAX-MIN)*sigmoid
    float lg = logf(fmaxf(gamma, 1e-8f));
    g_P[d * NR + r] = expf((float)d * lg);
    if (d < 64) g_Pinv[d * NR + r] = expf(-(float)d * lg);
    if (d == 0 && r == 0) {
        g_scal[0] = 1.0f / (1.0f + expf(-gate_logit[0]));   // gate
        g_scal[1] = 1.0f / (1.0f + expf(-alpha_logit[0]));  // alpha (ALPHA_CAP = 1)
    }
}

// ---------------------------------------------------------------------------
// RMSNorm: one block per row of D=1024
// grid: <<<NROWS, 256>>>
// ---------------------------------------------------------------------------
__global__ void k_rms(const float* __restrict__ x,
                      const float* __restrict__ scale,
                      float* __restrict__ y) {
    int row = blockIdx.x;
    const float4* xr = (const float4*)(x + (size_t)row * ND);
    float4 v = xr[threadIdx.x];
    float ss = v.x * v.x + v.y * v.y + v.z * v.z + v.w * v.w;
    #pragma unroll
    for (int o = 16; o; o >>= 1) ss += __shfl_xor_sync(0xffffffffu, ss, o);
    __shared__ float sp[8];
    __shared__ float s_rs;
    if ((threadIdx.x & 31) == 0) sp[threadIdx.x >> 5] = ss;
    __syncthreads();
    if (threadIdx.x == 0) {
        float t = 0.0f;
        #pragma unroll
        for (int i = 0; i < 8; i++) t += sp[i];
        s_rs = rsqrtf(t * (1.0f / (float)ND) + 1e-8f);
    }
    __syncthreads();
    float rs = s_rs;
    float4 sc = ((const float4*)scale)[threadIdx.x];
    float4 o;
    o.x = v.x * rs * sc.x;
    o.y = v.y * rs * sc.y;
    o.z = v.z * rs * sc.z;
    o.w = v.w * rs * sc.w;
    ((float4*)(y + (size_t)row * ND))[threadIdx.x] = o;
}

// ---------------------------------------------------------------------------
// qk = h_norm @ [u | v]  (8192x1024 @ 1024x128) then per-row L2 normalize
// halves -> g_q, g_k. Block: 64 rows x 128 cols, 256 threads, kc=32.
// grid: <<<NROWS/64, 256>>>
// ---------------------------------------------------------------------------
__global__ __launch_bounds__(256) void k_qk(const float* __restrict__ u,
                                            const float* __restrict__ v) {
    __shared__ float smem[8192];           // reused: [As 2048 | Bs 4096] then staging 8192
    __shared__ float s_scale[128];
    float* As = smem;                      // As[k][row] : 32 x 64
    float* Bs = smem + 2048;               // Bs[k][col] : 32 x 128
    int tid = threadIdx.x;
    int tx = tid & 15, ty = tid >> 4;
    int row0 = blockIdx.x * 64;

    float acc[4][8];
    #pragma unroll
    for (int i = 0; i < 4; i++)
        #pragma unroll
        for (int j = 0; j < 8; j++) acc[i][j] = 0.0f;

    for (int k0 = 0; k0 < ND; k0 += 32) {
        __syncthreads();
        // Load A tile (h_norm): 64 rows x 32 k, transposed into As[k][row]
        #pragma unroll
        for (int t = tid; t < 512; t += 256) {
            int r = t & 63, kq = t >> 6;   // kq 0..7
            float4 a = *(const float4*)(g_hnorm + (size_t)(row0 + r) * ND + k0 + kq * 4);
            As[(kq * 4 + 0) * 64 + r] = a.x;
            As[(kq * 4 + 1) * 64 + r] = a.y;
            As[(kq * 4 + 2) * 64 + r] = a.z;
            As[(kq * 4 + 3) * 64 + r] = a.w;
        }
        // Load B tile: Wqk[k][c] = (c<64 ? u[k][c] : v[k][c-64])
        #pragma unroll
        for (int t = tid; t < 1024; t += 256) {
            int cq = t & 31, kk = t >> 5;
            int c = cq * 4;
            const float* src = (c < 64) ? (u + (size_t)(k0 + kk) * NR + c)
                                        : (v + (size_t)(k0 + kk) * NR + (c - 64));
            *(float4*)(Bs + kk * 128 + c) = *(const float4*)src;
        }
        __syncthreads();
        #pragma unroll
        for (int kk = 0; kk < 32; kk++) {
            float a[4], b[8];
            *(float4*)a = *(const float4*)(As + kk * 64 + ty * 4);
            *(float4*)(b)     = *(const float4*)(Bs + kk * 128 + tx * 8);
            *(float4*)(b + 4) = *(const float4*)(Bs + kk * 128 + tx * 8 + 4);
            #pragma unroll
            for (int i = 0; i < 4; i++)
                #pragma unroll
                for (int j = 0; j < 8; j++) acc[i][j] = fmaf(a[i], b[j], acc[i][j]);
        }
    }
    __syncthreads();
    // Stage result in smem for row-wise L2 norms
    #pragma unroll
    for (int i = 0; i < 4; i++)
        #pragma unroll
        for (int j = 0; j < 8; j++)
            smem[(ty * 4 + i) * 128 + tx * 8 + j] = acc[i][j];
    __syncthreads();
    if (tid < 128) {
        int r = tid >> 1, half = tid & 1;
        float ssum = 0.0f;
        #pragma unroll 8
        for (int c = 0; c < 64; c++) {
            float x = smem[r * 128 + half * 64 + c];
            ssum += x * x;
        }
        s_scale[tid] = 1.0f / fmaxf(sqrtf(ssum), 1e-8f);  // F.normalize eps
    }
    __syncthreads();
    for (int t = tid; t < 8192; t += 256) {
        int r = t >> 7, c = t & 127;
        float val = smem[t] * s_scale[r * 2 + (c >= 64)];
        if (c < 64) g_q[(size_t)(row0 + r) * NR + c] = val;
        else        g_k[(size_t)(row0 + r) * NR + (c - 64)] = val;
    }
}

// ---------------------------------------------------------------------------
// Scores: M[b,i,j] = gate*k_base[i,j] + alpha * sum_r q[b,i,r] k[b,j,r] g_r^(i-j)
// causal (j<=i). Tile 64x64, decay factored via power tables.
// grid: <<<dim3(16,16,8), 256>>>, blocks with jt>it exit.
// ---------------------------------------------------------------------------
__global__ __launch_bounds__(256) void k_scores(const float* __restrict__ kbase) {
    int jt = blockIdx.x, it = blockIdx.y, b = blockIdx.z;
    if (jt > it) return;
    __shared__ float qs[64][65];
    __shared__ float ks[64][65];
    int iS = it * 64, jS = jt * 64;
    int tid = threadIdx.x;

    // qs[ii][r] = q[b, iS+ii, r] * gamma_r^(iS+ii - jS)
    for (int t = tid; t < 1024; t += 256) {
        int rq = t & 15, ii = t >> 4;
        int gi = iS + ii;
        float4 q4 = *(const float4*)(g_q + ((size_t)b * NW + gi) * NR + rq * 4);
        float4 p4 = *(const float4*)(g_P + (size_t)(gi - jS) * NR + rq * 4);
        qs[ii][rq * 4 + 0] = q4.x * p4.x;
        qs[ii][rq * 4 + 1] = q4.y * p4.y;
        qs[ii][rq * 4 + 2] = q4.z * p4.z;
        qs[ii][rq * 4 + 3] = q4.w * p4.w;
    }
    // ks[jj][r] = k[b, jS+jj, r] * gamma_r^(-jj)
    for (int t = tid; t < 1024; t += 256) {
        int rq = t & 15, jj = t >> 4;
        int gj = jS + jj;
        float4 k4 = *(const float4*)(g_k + ((size_t)b * NW + gj) * NR + rq * 4);
        float4 p4 = *(const float4*)(g_Pinv + jj * NR + rq * 4);
        ks[jj][rq * 4 + 0] = k4.x * p4.x;
        ks[jj][rq * 4 + 1] = k4.y * p4.y;
        ks[jj][rq * 4 + 2] = k4.z * p4.z;
        ks[jj][rq * 4 + 3] = k4.w * p4.w;
    }
    __syncthreads();
    int tx = tid & 15, ty = tid >> 4;
    float acc[4][4];
    #pragma unroll
    for (int i = 0; i < 4; i++)
        #pragma unroll
        for (int j = 0; j < 4; j++) acc[i][j] = 0.0f;
    #pragma unroll 4
    for (int r = 0; r < 64; r++) {
        float a[4], bb[4];
        #pragma unroll
        for (int i = 0; i < 4; i++) a[i] = qs[ty * 4 + i][r];
        #pragma unroll
        for (int j = 0; j < 4; j++) bb[j] = ks[tx * 4 + j][r];
        #pragma unroll
        for (int i = 0; i < 4; i++)
            #pragma unroll
            for (int j = 0; j < 4; j++) acc[i][j] = fmaf(a[i], bb[j], acc[i][j]);
    }
    float gate = g_scal[0], alpha = g_scal[1];
    #pragma unroll
    for (int i = 0; i < 4; i++) {
        int gi = iS + ty * 4 + i;
        #pragma unroll
        for (int j = 0; j < 4; j++) {
            int gj = jS + tx * 4 + j;
            float val = 0.0f;
            if (gi >= gj)
                val = gate * kbase[(size_t)gi * NW + gj] + alpha * acc[i][j];
            g_M[((size_t)b * NW + gi) * NW + gj] = val;
        }
    }
}

// ---------------------------------------------------------------------------
// attn = M @ h_norm  (causal: k-loop only up to row-tile end)
// Block: 64 i-rows x 128 d-cols, kc=16. grid: <<<dim3(8,16,8), 256>>>
// ---------------------------------------------------------------------------
__global__ __launch_bounds__(256) void k_attn_mm() {
    int dt = blockIdx.x, it = blockIdx.y, b = blockIdx.z;
    int iS = it * 64, d0 = dt * 128;
    __shared__ float As[16 * 64];    // As[k][row]
    __shared__ float Bs[16 * 128];   // Bs[k][d]
    int tid = threadIdx.x, tx = tid & 15, ty = tid >> 4;

    float acc[4][8];
    #pragma unroll
    for (int i = 0; i < 4; i++)
        #pragma unroll
        for (int j = 0; j < 8; j++) acc[i][j] = 0.0f;

    const float* Mb = g_M + (size_t)b * NW * NW;
    const float* H  = g_hnorm + (size_t)b * NW * ND;
    int kend = iS + 64;

    for (int k0 = 0; k0 < kend; k0 += 16) {
        __syncthreads();
        {   // A tile: 64 rows x 16 k, transposed store (256 tasks == 256 threads)
            int r = tid & 63, kq = tid >> 6;   // kq 0..3
            float4 a = *(const float4*)(Mb + (size_t)(iS + r) * NW + k0 + kq * 4);
            As[(kq * 4 + 0) * 64 + r] = a.x;
            As[(kq * 4 + 1) * 64 + r] = a.y;
            As[(kq * 4 + 2) * 64 + r] = a.z;
            As[(kq * 4 + 3) * 64 + r] = a.w;
        }
        #pragma unroll
        for (int t = tid; t < 512; t += 256) {  // B tile: 16 k x 128 d
            int dq = t & 31, kk = t >> 5;
            *(float4*)(Bs + kk * 128 + dq * 4) =
                *(const float4*)(H + (size_t)(k0 + kk) * ND + d0 + dq * 4);
        }
        __syncthreads();
        #pragma unroll
        for (int kk = 0; kk < 16; kk++) {
            float a[4], bb[8];
            *(float4*)a = *(const float4*)(As + kk * 64 + ty * 4);
            *(float4*)(bb)     = *(const float4*)(Bs + kk * 128 + tx * 8);
            *(float4*)(bb + 4) = *(const float4*)(Bs + kk * 128 + tx * 8 + 4);
            #pragma unroll
            for (int i = 0; i < 4; i++)
                #pragma unroll
                for (int j = 0; j < 8; j++) acc[i][j] = fmaf(a[i], bb[j], acc[i][j]);
        }
    }
    float* Ob = g_attn + (size_t)b * NW * ND;
    #pragma unroll
    for (int i = 0; i < 4; i++) {
        float4 o0 = make_float4(acc[i][0], acc[i][1], acc[i][2], acc[i][3]);
        float4 o1 = make_float4(acc[i][4], acc[i][5], acc[i][6], acc[i][7]);
        size_t base = (size_t)(iS + ty * 4 + i) * ND + d0 + tx * 8;
        *(float4*)(Ob + base)     = o0;
        *(float4*)(Ob + base + 4) = o1;
    }
}

// ---------------------------------------------------------------------------
// Generic NT GEMM: C[m,n] = sum_k A[m,k]*B[n,k] + bias[n] (+ add[m,n] | gelu)
// 128x128 tile, kc=16, 256 threads, 8x8 microtile.
// EPI: 0 => + add (residual), 1 => gelu exact
// grid: <<<dim3(N/128, M/128), 256>>>
// ---------------------------------------------------------------------------
__device__ __forceinline__ float gelu_exact(float x) {
    return 0.5f * x * (1.0f + erff(x * 0.70710678118654752f));
}

template <int EPI>
__global__ __launch_bounds__(256) void k_gemm_nt(const float* __restrict__ A,
                                                 const float* __restrict__ Bm,
                                                 const float* __restrict__ bias,
                                                 const float* __restrict__ add,
                                                 float* __restrict__ C,
                                                 int N, int K) {
    int n0 = blockIdx.x * 128, m0 = blockIdx.y * 128;
    __shared__ float As[16 * 128];   // As[k][m]
    __shared__ float Bs[16 * 128];   // Bs[k][n]
    int tid = threadIdx.x, tx = tid & 15, ty = tid >> 4;

    float acc[8][8];
    #pragma unroll
    for (int i = 0; i < 8; i++)
        #pragma unroll
        for (int j = 0; j < 8; j++) acc[i][j] = 0.0f;

    for (int k0 = 0; k0 < K; k0 += 16) {
        __syncthreads();
        #pragma unroll
        for (int t = tid; t < 512; t += 256) {
            int r = t & 127, kq = t >> 7;   // kq 0..3
            float4 a = *(const float4*)(A + (size_t)(m0 + r) * K + k0 + kq * 4);
            As[(kq * 4 + 0) * 128 + r] = a.x;
            As[(kq * 4 + 1) * 128 + r] = a.y;
            As[(kq * 4 + 2) * 128 + r] = a.z;
            As[(kq * 4 + 3) * 128 + r] = a.w;
        }
        #pragma unroll
        for (int t = tid; t < 512; t += 256) {
            int r = t & 127, kq = t >> 7;
            float4 bv = *(const float4*)(Bm + (size_t)(n0 + r) * K + k0 + kq * 4);
            Bs[(kq * 4 + 0) * 128 + r] = bv.x;
            Bs[(kq * 4 + 1) * 128 + r] = bv.y;
            Bs[(kq * 4 + 2) * 128 + r] = bv.z;
            Bs[(kq * 4 + 3) * 128 + r] = bv.w;
        }
        __syncthreads();
        #pragma unroll
        for (int kk = 0; kk < 16; kk++) {
            float a[8], b[8];
            *(float4*)(a)     = *(const float4*)(As + kk * 128 + ty * 8);
            *(float4*)(a + 4) = *(const float4*)(As + kk * 128 + ty * 8 + 4);
            *(float4*)(b)     = *(const float4*)(Bs + kk * 128 + tx * 8);
            *(float4*)(b + 4) = *(const float4*)(Bs + kk * 128 + tx * 8 + 4);
            #pragma unroll
            for (int i = 0; i < 8; i++)
                #pragma unroll
                for (int j = 0; j < 8; j++) acc[i][j] = fmaf(a[i], b[j], acc[i][j]);
        }
    }
    int m = m0 + ty * 8, n = n0 + tx * 8;
    float bv[8];
    *(float4*)(bv)     = *(const float4*)(bias + n);
    *(float4*)(bv + 4) = *(const float4*)(bias + n + 4);
    #pragma unroll
    for (int i = 0; i < 8; i++) {
        size_t base = (size_t)(m + i) * N + n;
        float o[8];
        if (EPI == 0) {
            float r[8];
            *(float4*)(r)     = *(const float4*)(add + base);
            *(float4*)(r + 4) = *(const float4*)(add + base + 4);
            #pragma unroll
            for (int j = 0; j < 8; j++) o[j] = acc[i][j] + bv[j] + r[j];
        } else {
            #pragma unroll
            for (int j = 0; j < 8; j++) o[j] = gelu_exact(acc[i][j] + bv[j]);
        }
        *(float4*)(C + base)     = make_float4(o[0], o[1], o[2], o[3]);
        *(float4*)(C + base + 4) = make_float4(o[4], o[5], o[6], o[7]);
    }
}

// ---------------------------------------------------------------------------
// Launch
// ---------------------------------------------------------------------------
extern "C" void kernel_launch(void* const* d_in, const int* in_sizes, int n_in,
                              void* d_out, int out_size) {
    const float* h           = (const float*)d_in[0];
    const float* k_base      = (const float*)d_in[1];
    const float* decay_logit = (const float*)d_in[2];
    const float* gate_logit  = (const float*)d_in[3];
    const float* alpha_logit = (const float*)d_in[4];
    const float* u           = (const float*)d_in[5];
    const float* v           = (const float*)d_in[6];
    const float* proj_w      = (const float*)d_in[7];
    const float* proj_b      = (const float*)d_in[8];
    const float* norm1       = (const float*)d_in[9];
    const float* norm2       = (const float*)d_in[10];
    const float* up_w        = (const float*)d_in[11];
    const float* up_b        = (const float*)d_in[12];
    const float* down_w      = (const float*)d_in[13];
    const float* down_b      = (const float*)d_in[14];
    float* out = (float*)d_out;

    float *p_hnorm, *p_h1, *p_mid, *p_t, *p_attn;
    cudaGetSymbolAddress((void**)&p_hnorm, g_hnorm);
    cudaGetSymbolAddress((void**)&p_h1,    g_h1);
    cudaGetSymbolAddress((void**)&p_mid,   g_mid);
    cudaGetSymbolAddress((void**)&p_t,     g_t);
    cudaGetSymbolAddress((void**)&p_attn,  g_attn);

    // 1. gamma power tables + gate/alpha scalars
    k_init<<<NW, NR>>>(decay_logit, gate_logit, alpha_logit);
    // 2. h_norm = rmsnorm(h, norm1)
    k_rms<<<NROWS, 256>>>(h, norm1, p_hnorm);
    // 3. q/k projections + L2 normalize
    k_qk<<<NROWS / 64, 256>>>(u, v);
    // 4. M = gate*kb + alpha*scores (causal, decay via tables)
    k_scores<<<dim3(16, 16, NB), 256>>>(k_base);
    // 5. attn = M @ h_norm (causal k-range)
    k_attn_mm<<<dim3(ND / 128, 16, NB), 256>>>();
    // 6. h1 = h + attn @ proj_w^T + proj_b
    k_gemm_nt<0><<<dim3(ND / 128, NROWS / 128), 256>>>(p_attn, proj_w, proj_b, h, p_h1, ND, ND);
    // 7. mid = rmsnorm(h1, norm2)
    k_rms<<<NROWS, 256>>>(p_h1, norm2, p_mid);
    // 8. t = gelu(mid @ up_w^T + up_b)
    k_gemm_nt<1><<<dim3(2 * ND / 128, NROWS / 128), 256>>>(p_mid, up_w, up_b, nullptr, p_t, 2 * ND, ND);
    // 9. out = h1 + t @ down_w^T + down_b
    k_gemm_nt<0><<<dim3(ND / 128, NROWS / 128), 256>>>(p_t, down_w, down_b, p_h1, out, ND, 2 * ND);
}

// round 7
// speedup vs baseline: 1.0004x; 1.0004x over previous
#include <cuda_runtime.h>
#include <math.h>

// Problem constants
#define NB 8
#define NW 1024
#define ND 1024
#define NR 64
#define NROWS (NB * NW)   // 8192

// ---------------------------------------------------------------------------
// Scratch (static __device__ arrays — no runtime allocation allowed)
// ---------------------------------------------------------------------------
__device__ float g_hnorm[NB * NW * ND];            // 32 MB
__device__ float g_q[NB * NW * NR];                // 2 MB
__device__ float g_k[NB * NW * NR];                // 2 MB
__device__ float g_M[NB * NW * NW];                // 32 MB  (gate*kb + alpha*scores, causal)
__device__ float g_attn[NB * NW * ND];             // 32 MB
__device__ float g_h1[NB * NW * ND];               // 32 MB
__device__ float g_mid[NB * NW * ND];              // 32 MB  (rmsnorm2 output)
__device__ float g_t[NB * NW * 2 * ND];            // 64 MB  (gelu(up) output)
__device__ float g_P[NW * NR];                     // gamma_r^d, d in [0,1024)
__device__ float g_Pinv[64 * NR];                  // gamma_r^-d, d in [0,64)
__device__ float g_scal[2];                        // gate, alpha

// ---------------------------------------------------------------------------
// Init: gamma tables + scalar gates
// grid: <<<1024, 64>>>
// ---------------------------------------------------------------------------
__global__ void k_init(const float* __restrict__ decay_logit,
                       const float* __restrict__ gate_logit,
                       const float* __restrict__ alpha_logit) {
    int r = threadIdx.x;      // 0..63
    int d = blockIdx.x;       // 0..1023
    float dl = decay_logit[r];
    float sg = 1.0f / (1.0f + expf(-dl));
    float gamma = 0.15f + 0.85f * sg;                 // GAMMA_MIN + (MAX-MIN)*sigmoid
    float lg = logf(fmaxf(gamma, 1e-8f));
    g_P[d * NR + r] = expf((float)d * lg);
    if (d < 64) g_Pinv[d * NR + r] = expf(-(float)d * lg);
    if (d == 0 && r == 0) {
        g_scal[0] = 1.0f / (1.0f + expf(-gate_logit[0]));   // gate
        g_scal[1] = 1.0f / (1.0f + expf(-alpha_logit[0]));  // alpha (ALPHA_CAP = 1)
    }
}

// ---------------------------------------------------------------------------
// RMSNorm: one block per row of D=1024
// grid: <<<NROWS, 256>>>
// ---------------------------------------------------------------------------
__global__ void k_rms(const float* __restrict__ x,
                      const float* __restrict__ scale,
                      float* __restrict__ y) {
    int row = blockIdx.x;
    const float4* xr = (const float4*)(x + (size_t)row * ND);
    float4 v = xr[threadIdx.x];
    float ss = v.x * v.x + v.y * v.y + v.z * v.z + v.w * v.w;
    #pragma unroll
    for (int o = 16; o; o >>= 1) ss += __shfl_xor_sync(0xffffffffu, ss, o);
    __shared__ float sp[8];
    __shared__ float s_rs;
    if ((threadIdx.x & 31) == 0) sp[threadIdx.x >> 5] = ss;
    __syncthreads();
    if (threadIdx.x == 0) {
        float t = 0.0f;
        #pragma unroll
        for (int i = 0; i < 8; i++) t += sp[i];
        s_rs = rsqrtf(t * (1.0f / (float)ND) + 1e-8f);
    }
    __syncthreads();
    float rs = s_rs;
    float4 sc = ((const float4*)scale)[threadIdx.x];
    float4 o;
    o.x = v.x * rs * sc.x;
    o.y = v.y * rs * sc.y;
    o.z = v.z * rs * sc.z;
    o.w = v.w * rs * sc.w;
    ((float4*)(y + (size_t)row * ND))[threadIdx.x] = o;
}

// ---------------------------------------------------------------------------
// qk = h_norm @ [u | v]  (8192x1024 @ 1024x128) then per-row L2 normalize
// halves -> g_q, g_k. Block: 64 rows x 128 cols, 256 threads, kc=32.
// grid: <<<NROWS/64, 256>>>
// ---------------------------------------------------------------------------
__global__ __launch_bounds__(256) void k_qk(const float* __restrict__ u,
                                            const float* __restrict__ v) {
    __shared__ float smem[8192];           // reused: [As 2048 | Bs 4096] then staging 8192
    __shared__ float s_scale[128];
    float* As = smem;                      // As[k][row] : 32 x 64
    float* Bs = smem + 2048;               // Bs[k][col] : 32 x 128
    int tid = threadIdx.x;
    int tx = tid & 15, ty = tid >> 4;
    int row0 = blockIdx.x * 64;

    float acc[4][8];
    #pragma unroll
    for (int i = 0; i < 4; i++)
        #pragma unroll
        for (int j = 0; j < 8; j++) acc[i][j] = 0.0f;

    for (int k0 = 0; k0 < ND; k0 += 32) {
        __syncthreads();
        // Load A tile (h_norm): 64 rows x 32 k, transposed into As[k][row]
        #pragma unroll
        for (int t = tid; t < 512; t += 256) {
            int r = t & 63, kq = t >> 6;   // kq 0..7
            float4 a = *(const float4*)(g_hnorm + (size_t)(row0 + r) * ND + k0 + kq * 4);
            As[(kq * 4 + 0) * 64 + r] = a.x;
            As[(kq * 4 + 1) * 64 + r] = a.y;
            As[(kq * 4 + 2) * 64 + r] = a.z;
            As[(kq * 4 + 3) * 64 + r] = a.w;
        }
        // Load B tile: Wqk[k][c] = (c<64 ? u[k][c] : v[k][c-64])
        #pragma unroll
        for (int t = tid; t < 1024; t += 256) {
            int cq = t & 31, kk = t >> 5;
            int c = cq * 4;
            const float* src = (c < 64) ? (u + (size_t)(k0 + kk) * NR + c)
                                        : (v + (size_t)(k0 + kk) * NR + (c - 64));
            *(float4*)(Bs + kk * 128 + c) = *(const float4*)src;
        }
        __syncthreads();
        #pragma unroll
        for (int kk = 0; kk < 32; kk++) {
            float a[4], b[8];
            *(float4*)a = *(const float4*)(As + kk * 64 + ty * 4);
            *(float4*)(b)     = *(const float4*)(Bs + kk * 128 + tx * 8);
            *(float4*)(b + 4) = *(const float4*)(Bs + kk * 128 + tx * 8 + 4);
            #pragma unroll
            for (int i = 0; i < 4; i++)
                #pragma unroll
                for (int j = 0; j < 8; j++) acc[i][j] = fmaf(a[i], b[j], acc[i][j]);
        }
    }
    __syncthreads();
    // Stage result in smem for row-wise L2 norms
    #pragma unroll
    for (int i = 0; i < 4; i++)
        #pragma unroll
        for (int j = 0; j < 8; j++)
            smem[(ty * 4 + i) * 128 + tx * 8 + j] = acc[i][j];
    __syncthreads();
    if (tid < 128) {
        int r = tid >> 1, half = tid & 1;
        float ssum = 0.0f;
        #pragma unroll 8
        for (int c = 0; c < 64; c++) {
            float x = smem[r * 128 + half * 64 + c];
            ssum += x * x;
        }
        s_scale[tid] = 1.0f / fmaxf(sqrtf(ssum), 1e-8f);  // F.normalize eps
    }
    __syncthreads();
    for (int t = tid; t < 8192; t += 256) {
        int r = t >> 7, c = t & 127;
        float val = smem[t] * s_scale[r * 2 + (c >= 64)];
        if (c < 64) g_q[(size_t)(row0 + r) * NR + c] = val;
        else        g_k[(size_t)(row0 + r) * NR + (c - 64)] = val;
    }
}

// ---------------------------------------------------------------------------
// Scores: M[b,i,j] = gate*k_base[i,j] + alpha * sum_r q[b,i,r] k[b,j,r] g_r^(i-j)
// causal (j<=i). Tile 64x64, decay factored via power tables.
// grid: <<<dim3(16,16,8), 256>>>, blocks with jt>it exit.
// ---------------------------------------------------------------------------
__global__ __launch_bounds__(256) void k_scores(const float* __restrict__ kbase) {
    int jt = blockIdx.x, it = blockIdx.y, b = blockIdx.z;
    if (jt > it) return;
    __shared__ float qs[64][65];
    __shared__ float ks[64][65];
    int iS = it * 64, jS = jt * 64;
    int tid = threadIdx.x;

    // qs[ii][r] = q[b, iS+ii, r] * gamma_r^(iS+ii - jS)
    for (int t = tid; t < 1024; t += 256) {
        int rq = t & 15, ii = t >> 4;
        int gi = iS + ii;
        float4 q4 = *(const float4*)(g_q + ((size_t)b * NW + gi) * NR + rq * 4);
        float4 p4 = *(const float4*)(g_P + (size_t)(gi - jS) * NR + rq * 4);
        qs[ii][rq * 4 + 0] = q4.x * p4.x;
        qs[ii][rq * 4 + 1] = q4.y * p4.y;
        qs[ii][rq * 4 + 2] = q4.z * p4.z;
        qs[ii][rq * 4 + 3] = q4.w * p4.w;
    }
    // ks[jj][r] = k[b, jS+jj, r] * gamma_r^(-jj)
    for (int t = tid; t < 1024; t += 256) {
        int rq = t & 15, jj = t >> 4;
        int gj = jS + jj;
        float4 k4 = *(const float4*)(g_k + ((size_t)b * NW + gj) * NR + rq * 4);
        float4 p4 = *(const float4*)(g_Pinv + jj * NR + rq * 4);
        ks[jj][rq * 4 + 0] = k4.x * p4.x;
        ks[jj][rq * 4 + 1] = k4.y * p4.y;
        ks[jj][rq * 4 + 2] = k4.z * p4.z;
        ks[jj][rq * 4 + 3] = k4.w * p4.w;
    }
    __syncthreads();
    int tx = tid & 15, ty = tid >> 4;
    float acc[4][4];
    #pragma unroll
    for (int i = 0; i < 4; i++)
        #pragma unroll
        for (int j = 0; j < 4; j++) acc[i][j] = 0.0f;
    #pragma unroll 4
    for (int r = 0; r < 64; r++) {
        float a[4], bb[4];
        #pragma unroll
        for (int i = 0; i < 4; i++) a[i] = qs[ty * 4 + i][r];
        #pragma unroll
        for (int j = 0; j < 4; j++) bb[j] = ks[tx * 4 + j][r];
        #pragma unroll
        for (int i = 0; i < 4; i++)
            #pragma unroll
            for (int j = 0; j < 4; j++) acc[i][j] = fmaf(a[i], bb[j], acc[i][j]);
    }
    float gate = g_scal[0], alpha = g_scal[1];
    #pragma unroll
    for (int i = 0; i < 4; i++) {
        int gi = iS + ty * 4 + i;
        #pragma unroll
        for (int j = 0; j < 4; j++) {
            int gj = jS + tx * 4 + j;
            float val = 0.0f;
            if (gi >= gj)
                val = gate * kbase[(size_t)gi * NW + gj] + alpha * acc[i][j];
            g_M[((size_t)b * NW + gi) * NW + gj] = val;
        }
    }
}

// ---------------------------------------------------------------------------
// attn = M @ h_norm  (causal: k-loop only up to row-tile end)
// Block: 64 i-rows x 128 d-cols, kc=16. grid: <<<dim3(8,16,8), 256>>>
// ---------------------------------------------------------------------------
__global__ __launch_bounds__(256) void k_attn_mm() {
    int dt = blockIdx.x, it = blockIdx.y, b = blockIdx.z;
    int iS = it * 64, d0 = dt * 128;
    __shared__ float As[16 * 64];    // As[k][row]
    __shared__ float Bs[16 * 128];   // Bs[k][d]
    int tid = threadIdx.x, tx = tid & 15, ty = tid >> 4;

    float acc[4][8];
    #pragma unroll
    for (int i = 0; i < 4; i++)
        #pragma unroll
        for (int j = 0; j < 8; j++) acc[i][j] = 0.0f;

    const float* Mb = g_M + (size_t)b * NW * NW;
    const float* H  = g_hnorm + (size_t)b * NW * ND;
    int kend = iS + 64;

    for (int k0 = 0; k0 < kend; k0 += 16) {
        __syncthreads();
        {   // A tile: 64 rows x 16 k, transposed store (256 tasks == 256 threads)
            int r = tid & 63, kq = tid >> 6;   // kq 0..3
            float4 a = *(const float4*)(Mb + (size_t)(iS + r) * NW + k0 + kq * 4);
            As[(kq * 4 + 0) * 64 + r] = a.x;
            As[(kq * 4 + 1) * 64 + r] = a.y;
            As[(kq * 4 + 2) * 64 + r] = a.z;
            As[(kq * 4 + 3) * 64 + r] = a.w;
        }
        #pragma unroll
        for (int t = tid; t < 512; t += 256) {  // B tile: 16 k x 128 d
            int dq = t & 31, kk = t >> 5;
            *(float4*)(Bs + kk * 128 + dq * 4) =
                *(const float4*)(H + (size_t)(k0 + kk) * ND + d0 + dq * 4);
        }
        __syncthreads();
        #pragma unroll
        for (int kk = 0; kk < 16; kk++) {
            float a[4], bb[8];
            *(float4*)a = *(const float4*)(As + kk * 64 + ty * 4);
            *(float4*)(bb)     = *(const float4*)(Bs + kk * 128 + tx * 8);
            *(float4*)(bb + 4) = *(const float4*)(Bs + kk * 128 + tx * 8 + 4);
            #pragma unroll
            for (int i = 0; i < 4; i++)
                #pragma unroll
                for (int j = 0; j < 8; j++) acc[i][j] = fmaf(a[i], bb[j], acc[i][j]);
        }
    }
    float* Ob = g_attn + (size_t)b * NW * ND;
    #pragma unroll
    for (int i = 0; i < 4; i++) {
        float4 o0 = make_float4(acc[i][0], acc[i][1], acc[i][2], acc[i][3]);
        float4 o1 = make_float4(acc[i][4], acc[i][5], acc[i][6], acc[i][7]);
        size_t base = (size_t)(iS + ty * 4 + i) * ND + d0 + tx * 8;
        *(float4*)(Ob + base)     = o0;
        *(float4*)(Ob + base + 4) = o1;
    }
}

// ---------------------------------------------------------------------------
// Generic NT GEMM: C[m,n] = sum_k A[m,k]*B[n,k] + bias[n] (+ add[m,n] | gelu)
// 128x128 tile, kc=16, 256 threads, 8x8 microtile.
// EPI: 0 => + add (residual), 1 => gelu exact
// grid: <<<dim3(N/128, M/128), 256>>>
// ---------------------------------------------------------------------------
__device__ __forceinline__ float gelu_exact(float x) {
    return 0.5f * x * (1.0f + erff(x * 0.70710678118654752f));
}

template <int EPI>
__global__ __launch_bounds__(256) void k_gemm_nt(const float* __restrict__ A,
                                                 const float* __restrict__ Bm,
                                                 const float* __restrict__ bias,
                                                 const float* __restrict__ add,
                                                 float* __restrict__ C,
                                                 int N, int K) {
    int n0 = blockIdx.x * 128, m0 = blockIdx.y * 128;
    __shared__ float As[16 * 128];   // As[k][m]
    __shared__ float Bs[16 * 128];   // Bs[k][n]
    int tid = threadIdx.x, tx = tid & 15, ty = tid >> 4;

    float acc[8][8];
    #pragma unroll
    for (int i = 0; i < 8; i++)
        #pragma unroll
        for (int j = 0; j < 8; j++) acc[i][j] = 0.0f;

    for (int k0 = 0; k0 < K; k0 += 16) {
        __syncthreads();
        #pragma unroll
        for (int t = tid; t < 512; t += 256) {
            int r = t & 127, kq = t >> 7;   // kq 0..3
            float4 a = *(const float4*)(A + (size_t)(m0 + r) * K + k0 + kq * 4);
            As[(kq * 4 + 0) * 128 + r] = a.x;
            As[(kq * 4 + 1) * 128 + r] = a.y;
            As[(kq * 4 + 2) * 128 + r] = a.z;
            As[(kq * 4 + 3) * 128 + r] = a.w;
        }
        #pragma unroll
        for (int t = tid; t < 512; t += 256) {
            int r = t & 127, kq = t >> 7;
            float4 bv = *(const float4*)(Bm + (size_t)(n0 + r) * K + k0 + kq * 4);
            Bs[(kq * 4 + 0) * 128 + r] = bv.x;
            Bs[(kq * 4 + 1) * 128 + r] = bv.y;
            Bs[(kq * 4 + 2) * 128 + r] = bv.z;
            Bs[(kq * 4 + 3) * 128 + r] = bv.w;
        }
        __syncthreads();
        #pragma unroll
        for (int kk = 0; kk < 16; kk++) {
            float a[8], b[8];
            *(float4*)(a)     = *(const float4*)(As + kk * 128 + ty * 8);
            *(float4*)(a + 4) = *(const float4*)(As + kk * 128 + ty * 8 + 4);
            *(float4*)(b)     = *(const float4*)(Bs + kk * 128 + tx * 8);
            *(float4*)(b + 4) = *(const float4*)(Bs + kk * 128 + tx * 8 + 4);
            #pragma unroll
            for (int i = 0; i < 8; i++)
                #pragma unroll
                for (int j = 0; j < 8; j++) acc[i][j] = fmaf(a[i], b[j], acc[i][j]);
        }
    }
    int m = m0 + ty * 8, n = n0 + tx * 8;
    float bv[8];
    *(float4*)(bv)     = *(const float4*)(bias + n);
    *(float4*)(bv + 4) = *(const float4*)(bias + n + 4);
    #pragma unroll
    for (int i = 0; i < 8; i++) {
        size_t base = (size_t)(m + i) * N + n;
        float o[8];
        if (EPI == 0) {
            float r[8];
            *(float4*)(r)     = *(const float4*)(add + base);
            *(float4*)(r + 4) = *(const float4*)(add + base + 4);
            #pragma unroll
            for (int j = 0; j < 8; j++) o[j] = acc[i][j] + bv[j] + r[j];
        } else {
            #pragma unroll
            for (int j = 0; j < 8; j++) o[j] = gelu_exact(acc[i][j] + bv[j]);
        }
        *(float4*)(C + base)     = make_float4(o[0], o[1], o[2], o[3]);
        *(float4*)(C + base + 4) = make_float4(o[4], o[5], o[6], o[7]);
    }
}

// ---------------------------------------------------------------------------
// Launch
// ---------------------------------------------------------------------------
extern "C" void kernel_launch(void* const* d_in, const int* in_sizes, int n_in,
                              void* d_out, int out_size) {
    const float* h           = (const float*)d_in[0];
    const float* k_base      = (const float*)d_in[1];
    const float* decay_logit = (const float*)d_in[2];
    const float* gate_logit  = (const float*)d_in[3];
    const float* alpha_logit = (const float*)d_in[4];
    const float* u           = (const float*)d_in[5];
    const float* v           = (const float*)d_in[6];
    const float* proj_w      = (const float*)d_in[7];
    const float* proj_b      = (const float*)d_in[8];
    const float* norm1       = (const float*)d_in[9];
    const float* norm2       = (const float*)d_in[10];
    const float* up_w        = (const float*)d_in[11];
    const float* up_b        = (const float*)d_in[12];
    const float* down_w      = (const float*)d_in[13];
    const float* down_b      = (const float*)d_in[14];
    float* out = (float*)d_out;

    float *p_hnorm, *p_h1, *p_mid, *p_t, *p_attn;
    cudaGetSymbolAddress((void**)&p_hnorm, g_hnorm);
    cudaGetSymbolAddress((void**)&p_h1,    g_h1);
    cudaGetSymbolAddress((void**)&p_mid,   g_mid);
    cudaGetSymbolAddress((void**)&p_t,     g_t);
    cudaGetSymbolAddress((void**)&p_attn,  g_attn);

    // 1. gamma power tables + gate/alpha scalars
    k_init<<<NW, NR>>>(decay_logit, gate_logit, alpha_logit);
    // 2. h_norm = rmsnorm(h, norm1)
    k_rms<<<NROWS, 256>>>(h, norm1, p_hnorm);
    // 3. q/k projections + L2 normalize
    k_qk<<<NROWS / 64, 256>>>(u, v);
    // 4. M = gate*kb + alpha*scores (causal, decay via tables)
    k_scores<<<dim3(16, 16, NB), 256>>>(k_base);
    // 5. attn = M @ h_norm (causal k-range)
    k_attn_mm<<<dim3(ND / 128, 16, NB), 256>>>();
    // 6. h1 = h + attn @ proj_w^T + proj_b
    k_gemm_nt<0><<<dim3(ND / 128, NROWS / 128), 256>>>(p_attn, proj_w, proj_b, h, p_h1, ND, ND);
    // 7. mid = rmsnorm(h1, norm2)
    k_rms<<<NROWS, 256>>>(p_h1, norm2, p_mid);
    // 8. t = gelu(mid @ up_w^T + up_b)
    k_gemm_nt<1><<<dim3(2 * ND / 128, NROWS / 128), 256>>>(p_mid, up_w, up_b, nullptr, p_t, 2 * ND, ND);
    // 9. out = h1 + t @ down_w^T + down_b
    k_gemm_nt<0><<<dim3(ND / 128, NROWS / 128), 256>>>(p_t, down_w, down_b, p_h1, out, ND, 2 * ND);
}